// round 16
// baseline (speedup 1.0000x reference)
#include <cuda_runtime.h>
#include <cuda_fp16.h>
#include <cuda_fp8.h>

typedef unsigned int u32;
typedef unsigned char u8;

#define BB 8
#define CC 512
#define TT 4096
#define SCALE_F 0.125f
#define NELEM ((size_t)BB * CC * TT)
#define CCSQ ((size_t)CC * CC)
#define KSPL_G 4

// ---------------- scratch ----------------
__device__ half g_x_h[NELEM];
__device__ half g_x_l[NELEM];
__device__ u8   g_x_h8[NELEM];
__device__ u8   g_x_l8[NELEM];
__device__ half g_wq_h[CCSQ];
__device__ half g_wq_l[CCSQ];
__device__ u8   g_wq_h8[CCSQ];
__device__ u8   g_wq_l8[CCSQ];
__device__ half g_wk_h[CCSQ];
__device__ half g_wk_l[CCSQ];
__device__ u8   g_wk_h8[CCSQ];
__device__ u8   g_wk_l8[CCSQ];
__device__ half g_wv_h[CCSQ];
__device__ half g_wv_l[CCSQ];
__device__ float g_part[(size_t)KSPL_G * BB * CCSQ];
__device__ half g_G_h[(size_t)BB * CCSQ];
__device__ half g_G_l[(size_t)BB * CCSQ];
__device__ u8   g_G_h8[(size_t)BB * CCSQ];
__device__ u8   g_G_l8[(size_t)BB * CCSQ];
__device__ half g_t2_h[(size_t)BB * CCSQ];
__device__ half g_t2_l[(size_t)BB * CCSQ];
__device__ u8   g_t2_h8[(size_t)BB * CCSQ];
__device__ u8   g_t2_l8[(size_t)BB * CCSQ];
__device__ float g_dots[(size_t)BB * CCSQ];
__device__ half g_a_h[(size_t)BB * CCSQ];
__device__ half g_P_h[(size_t)BB * CCSQ];
__device__ half g_P_l[(size_t)BB * CCSQ];
__device__ float g_sx[BB * CC];
__device__ float g_w1[BB * CC];
__device__ float g_w2[BB * CC];
__device__ float g_pb[BB * CC];

// upper-triangle 128-tile map for G (4x4 tiles -> 10)
__device__ __constant__ int c_ti[10] = {0, 0, 0, 0, 1, 1, 1, 2, 2, 3};
__device__ __constant__ int c_tj[10] = {0, 1, 2, 3, 1, 2, 3, 2, 3, 3};

// ---------------- helpers ----------------
__device__ __forceinline__ u32 smem_u32(const void* p) {
    u32 a;
    asm("{ .reg .u64 t; cvta.to.shared.u64 t, %1; cvt.u32.u64 %0, t; }" : "=r"(a) : "l"(p));
    return a;
}
__device__ __forceinline__ u8 to8(float v) {
    __nv_fp8_e4m3 t(v);
    return *reinterpret_cast<u8*>(&t);
}
__device__ __forceinline__ void split2h(float a, float b, u32& h, u32& l) {
    __half h0 = __float2half_rn(a), h1 = __float2half_rn(b);
    __half l0 = __float2half_rn(a - __half2float(h0));
    __half l1 = __float2half_rn(b - __half2float(h1));
    __half2 hh = __halves2half2(h0, h1), ll = __halves2half2(l0, l1);
    h = *(u32*)&hh;
    l = *(u32*)&ll;
}
__device__ __forceinline__ void pack2h(float a, float b, u32& h) {
    __half2 hh = __halves2half2(__float2half_rn(a), __float2half_rn(b));
    h = *(u32*)&hh;
}
__device__ __forceinline__ void ldsm4(u32& r0, u32& r1, u32& r2, u32& r3, u32 addr) {
    asm volatile("ldmatrix.sync.aligned.m8n8.x4.shared.b16 {%0,%1,%2,%3}, [%4];"
                 : "=r"(r0), "=r"(r1), "=r"(r2), "=r"(r3) : "r"(addr));
}
__device__ __forceinline__ void ldsm4t(u32& r0, u32& r1, u32& r2, u32& r3, u32 addr) {
    asm volatile("ldmatrix.sync.aligned.m8n8.x4.trans.shared.b16 {%0,%1,%2,%3}, [%4];"
                 : "=r"(r0), "=r"(r1), "=r"(r2), "=r"(r3) : "r"(addr));
}
__device__ __forceinline__ void mma16816(float* d, const u32* a, u32 b0, u32 b1) {
    asm volatile(
        "mma.sync.aligned.m16n8k16.row.col.f32.f16.f16.f32 "
        "{%0,%1,%2,%3}, {%4,%5,%6,%7}, {%8,%9}, {%0,%1,%2,%3};"
        : "+f"(d[0]), "+f"(d[1]), "+f"(d[2]), "+f"(d[3])
        : "r"(a[0]), "r"(a[1]), "r"(a[2]), "r"(a[3]), "r"(b0), "r"(b1));
}
// fp8 e4m3 k32 MMA (2x MACs per instruction vs f16 k16)
__device__ __forceinline__ void mma16832q(float* d, const u32* a, u32 b0, u32 b1) {
    asm volatile(
        "mma.sync.aligned.m16n8k32.row.col.f32.e4m3.e4m3.f32 "
        "{%0,%1,%2,%3}, {%4,%5,%6,%7}, {%8,%9}, {%0,%1,%2,%3};"
        : "+f"(d[0]), "+f"(d[1]), "+f"(d[2]), "+f"(d[3])
        : "r"(a[0]), "r"(a[1]), "r"(a[2]), "r"(a[3]), "r"(b0), "r"(b1));
}
// cp.async 128 rows x 64 half (128B rows), SW swizzle; 256 threads.
__device__ __forceinline__ void cp_tile(u32 sdst, const half* g, int ld, int tid) {
    const int seg = tid & 7;
    const int r0 = tid >> 3;
    const char* gc = (const char*)g + seg * 16;
#pragma unroll
    for (int p = 0; p < 4; p++) {
        int row = p * 32 + r0;
        u32 dst = sdst + row * 128 + ((seg ^ (row & 7)) << 4);
        const void* src = gc + (size_t)row * ld * sizeof(half);
        asm volatile("cp.async.cg.shared.global [%0], [%1], 16;" :: "r"(dst), "l"(src) : "memory");
    }
}
// cp.async 128 rows x 64 fp8 (64B rows); 256 threads, 2 passes.
__device__ __forceinline__ void cp_tile8(u32 sdst, const u8* g, int ld, int tid) {
    const int seg = tid & 3;
    const int r0 = tid >> 2;           // 0..63
    const u8* gc = g + seg * 16;
#pragma unroll
    for (int p = 0; p < 2; p++) {
        int row = p * 64 + r0;
        u32 dst = sdst + row * 64 + ((seg ^ (row & 3)) << 4);
        const void* src = gc + (size_t)row * ld;
        asm volatile("cp.async.cg.shared.global [%0], [%1], 16;" :: "r"(dst), "l"(src) : "memory");
    }
}
// cp.async 64 rows x 128 half (256B rows); 256 threads.
__device__ __forceinline__ void cp_tileB(u32 sdst, const half* g, int ld, int tid) {
    const int seg = tid & 15;
    const int r0 = tid >> 4;
    const char* gc = (const char*)g + seg * 16;
#pragma unroll
    for (int p = 0; p < 4; p++) {
        int row = p * 16 + r0;
        u32 dst = sdst + row * 256 + ((seg ^ (row & 7)) << 4);
        const void* src = gc + (size_t)row * ld * sizeof(half);
        asm volatile("cp.async.cg.shared.global [%0], [%1], 16;" :: "r"(dst), "l"(src) : "memory");
    }
}

// ---------------------------------------------------------------------------
// GEMM D[m,n] = scale*(A.B) + bias; fp16 2-term split.
// NPROD=3: AhBh in f16 (f32 acc) + cross terms (AlBh + AhBl) in fp8 e4m3 k32
//   at 2x MACs/instruction. fp8 scaling: h8 = e4m3(v/16), l8 = e4m3(l*128);
//   cross product = 8x true value -> epilogue adds accq * 0.125.
// NPROD=1: AhBh only.
// BM=128, BN=128, BK=64. 8 warps (4M x 2N). 2-stage cp.async.
// BTRANS: B is [k][n] n-contig via ldmatrix.trans (NPROD=1 only).
// TRI: triangular G grid.
// ---------------------------------------------------------------------------
template <bool BIASROW, bool SPLIT, int KSPL, bool TRI, bool BTRANS, int NPROD>
__global__ __launch_bounds__(256) void gemm_mma(
    const half* __restrict__ Ah, const half* __restrict__ Al,
    const u8* __restrict__ Ah8, const u8* __restrict__ Al8, size_t sA, int lda,
    const half* __restrict__ Bh, const half* __restrict__ Bl,
    const u8* __restrict__ Bh8, const u8* __restrict__ Bl8, size_t sB, int ldb,
    float* __restrict__ C, half* __restrict__ Ch, half* __restrict__ Cl,
    u8* __restrict__ Ch8, u8* __restrict__ Cl8,
    size_t sC, int ldc, const float* __restrict__ bias, int biasZ,
    float scale, int K)
{
    // stage layout: Ah 16K | Bh 16K | [a_h8 8K | a_l8 8K | b_h8 8K | b_l8 8K]
    constexpr u32 STAGE = (NPROD == 3) ? 65536 : 32768;

    extern __shared__ char dyn[];
    char* dg = (char*)(((size_t)dyn + 1023) & ~(size_t)1023);
    const u32 base = smem_u32(dg);

    const int tid = threadIdx.x, wid = tid >> 5, lane = tid & 31;
    const int z = blockIdx.z;
    const int batch = z / KSPL, ksl = z - batch * KSPL;
    const int m0 = TRI ? c_ti[blockIdx.x] * 128 : blockIdx.y * 128;
    const int n0 = TRI ? c_tj[blockIdx.x] * 128 : blockIdx.x * 128;
    const int wm = wid & 3, wn = wid >> 2;

    const size_t aoff = (size_t)batch * sA + (size_t)ksl * K + (size_t)m0 * lda;
    const half* pAh = Ah + aoff;
    const u8* pAh8 = (NPROD == 3) ? Ah8 + aoff : nullptr;
    const u8* pAl8 = (NPROD == 3) ? Al8 + aoff : nullptr;
    const half* pBh;
    const u8 *pBh8 = nullptr, *pBl8 = nullptr;
    if (BTRANS) {
        pBh = Bh + (size_t)batch * sB + (size_t)(ksl * K) * ldb + n0;
    } else {
        const size_t boff = (size_t)batch * sB + (size_t)ksl * K + (size_t)n0 * ldb;
        pBh = Bh + boff;
        if (NPROD == 3) { pBh8 = Bh8 + boff; pBl8 = Bl8 + boff; }
    }

    const int NCH = K >> 6;

    float acc[2][8][4];
#pragma unroll
    for (int i = 0; i < 2; i++)
#pragma unroll
        for (int j = 0; j < 8; j++)
#pragma unroll
            for (int t = 0; t < 4; t++) acc[i][j][t] = 0.0f;

    float accq[2][8][4];
    if (NPROD == 3) {
#pragma unroll
        for (int i = 0; i < 2; i++)
#pragma unroll
            for (int j = 0; j < 8; j++)
#pragma unroll
                for (int t = 0; t < 4; t++) accq[i][j][t] = 0.0f;
    }

    // prologue: stage 0
    cp_tile(base, pAh, lda, tid);
    if (BTRANS) cp_tileB(base + 16384, pBh, ldb, tid);
    else        cp_tile(base + 16384, pBh, ldb, tid);
    if (NPROD == 3) {
        cp_tile8(base + 32768, pAh8, lda, tid);
        cp_tile8(base + 40960, pAl8, lda, tid);
        cp_tile8(base + 49152, pBh8, ldb, tid);
        cp_tile8(base + 57344, pBl8, ldb, tid);
    }
    asm volatile("cp.async.commit_group;" ::: "memory");

    for (int c = 0; c < NCH; c++) {
        const int st = c & 1;
        if (c + 1 < NCH) {
            const u32 sb = base + (st ^ 1) * STAGE;
            const int ko = (c + 1) * 64;
            cp_tile(sb, pAh + ko, lda, tid);
            if (BTRANS) cp_tileB(sb + 16384, pBh + (size_t)ko * ldb, ldb, tid);
            else        cp_tile(sb + 16384, pBh + ko, ldb, tid);
            if (NPROD == 3) {
                cp_tile8(sb + 32768, pAh8 + ko, lda, tid);
                cp_tile8(sb + 40960, pAl8 + ko, lda, tid);
                cp_tile8(sb + 49152, pBh8 + ko, ldb, tid);
                cp_tile8(sb + 57344, pBl8 + ko, ldb, tid);
            }
        }
        asm volatile("cp.async.commit_group;" ::: "memory");
        asm volatile("cp.async.wait_group 1;" ::: "memory");
        __syncthreads();

        const u32 sAh = base + st * STAGE;
        const u32 sBh = sAh + 16384;
        const u32 sAh8 = sAh + 32768, sAl8 = sAh + 40960;
        const u32 sBh8 = sAh + 49152, sBl8 = sAh + 57344;

        // ---- main product: f16, f32 accumulate ----
#pragma unroll
        for (int ks = 0; ks < 4; ks++) {
            u32 ah[2][4];
#pragma unroll
            for (int mi = 0; mi < 2; mi++) {
                const int row = wm * 32 + mi * 16 + (lane & 15);
                const u32 off = row * 128 + ((((ks << 1) | (lane >> 4)) ^ (row & 7)) << 4);
                ldsm4(ah[mi][0], ah[mi][1], ah[mi][2], ah[mi][3], sAh + off);
            }
            u32 bh[4][4];
#pragma unroll
            for (int ni = 0; ni < 4; ni++) {
                if (BTRANS) {
                    const int row = ks * 16 + (lane & 15);
                    const int chunk = wn * 8 + ni * 2 + (lane >> 4);
                    const u32 off = row * 256 + ((chunk ^ (row & 7)) << 4);
                    ldsm4t(bh[ni][0], bh[ni][1], bh[ni][2], bh[ni][3], sBh + off);
                } else {
                    const int row = wn * 64 + ni * 16 + (lane & 15);
                    const u32 off = row * 128 + ((((ks << 1) | (lane >> 4)) ^ (row & 7)) << 4);
                    ldsm4(bh[ni][0], bh[ni][1], bh[ni][2], bh[ni][3], sBh + off);
                }
            }
            const int p0 = BTRANS ? 1 : 2;
            const int q0 = BTRANS ? 2 : 1;
#pragma unroll
            for (int mi = 0; mi < 2; mi++)
#pragma unroll
                for (int ni = 0; ni < 4; ni++) {
                    mma16816(acc[mi][2 * ni + 0], ah[mi], bh[ni][0], bh[ni][p0]);
                    mma16816(acc[mi][2 * ni + 1], ah[mi], bh[ni][q0], bh[ni][3]);
                }
        }

        // ---- cross products: fp8 e4m3 k32 (2 steps cover BK=64) ----
        if (NPROD == 3) {
#pragma unroll
            for (int ks = 0; ks < 2; ks++) {
                u32 a8h[2][4], a8l[2][4];
#pragma unroll
                for (int mi = 0; mi < 2; mi++) {
                    const int row = wm * 32 + mi * 16 + (lane & 15);
                    const u32 off = row * 64 + ((((ks << 1) | (lane >> 4)) ^ (row & 3)) << 4);
                    ldsm4(a8h[mi][0], a8h[mi][1], a8h[mi][2], a8h[mi][3], sAh8 + off);
                    ldsm4(a8l[mi][0], a8l[mi][1], a8l[mi][2], a8l[mi][3], sAl8 + off);
                }
                u32 b8h[4][4], b8l[4][4];
#pragma unroll
                for (int ni = 0; ni < 4; ni++) {
                    const int row = wn * 64 + ni * 16 + (lane & 15);
                    const u32 off = row * 64 + ((((ks << 1) | (lane >> 4)) ^ (row & 3)) << 4);
                    ldsm4(b8h[ni][0], b8h[ni][1], b8h[ni][2], b8h[ni][3], sBh8 + off);
                    ldsm4(b8l[ni][0], b8l[ni][1], b8l[ni][2], b8l[ni][3], sBl8 + off);
                }
#pragma unroll
                for (int mi = 0; mi < 2; mi++)
#pragma unroll
                    for (int ni = 0; ni < 4; ni++) {
                        mma16832q(accq[mi][2 * ni + 0], a8l[mi], b8h[ni][0], b8h[ni][2]);
                        mma16832q(accq[mi][2 * ni + 1], a8l[mi], b8h[ni][1], b8h[ni][3]);
                        mma16832q(accq[mi][2 * ni + 0], a8h[mi], b8l[ni][0], b8l[ni][2]);
                        mma16832q(accq[mi][2 * ni + 1], a8h[mi], b8l[ni][1], b8l[ni][3]);
                    }
            }
        }
        __syncthreads();
    }

    // epilogue
    const int mwarp = m0 + wm * 32;
    const int nwarp = n0 + wn * 64;
#pragma unroll
    for (int mi = 0; mi < 2; mi++) {
        const int r0 = mwarp + mi * 16 + (lane >> 2);
        float br0 = 0.f, br1 = 0.f;
        if (BIASROW) { br0 = bias[z * biasZ + r0]; br1 = bias[z * biasZ + r0 + 8]; }
#pragma unroll
        for (int nj = 0; nj < 8; nj++) {
            const int col = nwarp + nj * 8 + (lane & 3) * 2;
            const float* d = acc[mi][nj];
            float e0 = 0.f, e1 = 0.f, e2 = 0.f, e3 = 0.f;
            if (NPROD == 3) {
                const float* q = accq[mi][nj];
                e0 = q[0] * 0.125f; e1 = q[1] * 0.125f;
                e2 = q[2] * 0.125f; e3 = q[3] * 0.125f;
            }
            float v00 = (d[0] + e0) * scale + br0;
            float v01 = (d[1] + e1) * scale + br0;
            float v10 = (d[2] + e2) * scale + br1;
            float v11 = (d[3] + e3) * scale + br1;
            const size_t i0 = (size_t)z * sC + (size_t)r0 * ldc + col;
            const size_t i1 = i0 + (size_t)8 * ldc;
            if (SPLIT) {
                if (Cl) {
                    u32 h, l;
                    split2h(v00, v01, h, l);
                    *(u32*)(Ch + i0) = h; *(u32*)(Cl + i0) = l;
                    split2h(v10, v11, h, l);
                    *(u32*)(Ch + i1) = h; *(u32*)(Cl + i1) = l;
                    if (Ch8) {
                        float h00 = __half2float(__float2half_rn(v00));
                        float h01 = __half2float(__float2half_rn(v01));
                        float h10 = __half2float(__float2half_rn(v10));
                        float h11 = __half2float(__float2half_rn(v11));
                        *(unsigned short*)(Ch8 + i0) =
                            (unsigned short)(to8(v00 * 0.0625f) | (to8(v01 * 0.0625f) << 8));
                        *(unsigned short*)(Cl8 + i0) =
                            (unsigned short)(to8((v00 - h00) * 128.f) | (to8((v01 - h01) * 128.f) << 8));
                        *(unsigned short*)(Ch8 + i1) =
                            (unsigned short)(to8(v10 * 0.0625f) | (to8(v11 * 0.0625f) << 8));
                        *(unsigned short*)(Cl8 + i1) =
                            (unsigned short)(to8((v10 - h10) * 128.f) | (to8((v11 - h11) * 128.f) << 8));
                    }
                } else {
                    u32 h;
                    pack2h(v00, v01, h); *(u32*)(Ch + i0) = h;
                    pack2h(v10, v11, h); *(u32*)(Ch + i1) = h;
                }
            } else {
                *(float2*)(C + i0) = make_float2(v00, v01);
                *(float2*)(C + i1) = make_float2(v10, v11);
            }
        }
    }
}

// ---------------- elementwise kernels ----------------
__global__ void xsplit_sum(const float* __restrict__ x, half* __restrict__ xh,
                           half* __restrict__ xl, u8* __restrict__ xh8,
                           u8* __restrict__ xl8, float* __restrict__ sx)
{
    const int r = blockIdx.x, tid = threadIdx.x;
    const float4* in = (const float4*)(x + (size_t)r * TT);
    uint2* oh = (uint2*)(xh + (size_t)r * TT);
    uint2* ol = (uint2*)(xl + (size_t)r * TT);
    u32* oh8 = (u32*)(xh8 + (size_t)r * TT);
    u32* ol8 = (u32*)(xl8 + (size_t)r * TT);
    float sum = 0.f;
#pragma unroll
    for (int i = 0; i < 4; i++) {
        const int idx = tid + i * 256;
        float4 v = in[idx];
        sum += v.x + v.y + v.z + v.w;
        uint2 h, l;
        split2h(v.x, v.y, h.x, l.x);
        split2h(v.z, v.w, h.y, l.y);
        oh[idx] = h;
        ol[idx] = l;
        float hx = __half2float(__float2half_rn(v.x));
        float hy = __half2float(__float2half_rn(v.y));
        float hz = __half2float(__float2half_rn(v.z));
        float hw = __half2float(__float2half_rn(v.w));
        oh8[idx] = (u32)to8(v.x * 0.0625f) | ((u32)to8(v.y * 0.0625f) << 8) |
                   ((u32)to8(v.z * 0.0625f) << 16) | ((u32)to8(v.w * 0.0625f) << 24);
        ol8[idx] = (u32)to8((v.x - hx) * 128.f) | ((u32)to8((v.y - hy) * 128.f) << 8) |
                   ((u32)to8((v.z - hz) * 128.f) << 16) | ((u32)to8((v.w - hw) * 128.f) << 24);
    }
#pragma unroll
    for (int o = 16; o > 0; o >>= 1) sum += __shfl_xor_sync(~0u, sum, o);
    __shared__ float red[8];
    if ((tid & 31) == 0) red[tid >> 5] = sum;
    __syncthreads();
    if (tid == 0) {
        float t = 0.f;
#pragma unroll
        for (int i = 0; i < 8; i++) t += red[i];
        sx[r] = t;
    }
}

// split 3 weight matrices (fp8 outputs only for Wq, Wk)
__global__ void esplit3(const float* __restrict__ w0, const float* __restrict__ w1,
                        const float* __restrict__ w2, half* __restrict__ oh0,
                        half* __restrict__ ol0, half* __restrict__ oh1,
                        half* __restrict__ ol1, half* __restrict__ oh2,
                        half* __restrict__ ol2, u8* __restrict__ oh80,
                        u8* __restrict__ ol80, u8* __restrict__ oh81,
                        u8* __restrict__ ol81)
{
    const int which = blockIdx.y;
    const float* in = which == 0 ? w0 : (which == 1 ? w1 : w2);
    half* oh = which == 0 ? oh0 : (which == 1 ? oh1 : oh2);
    half* ol = which == 0 ? ol0 : (which == 1 ? ol1 : ol2);
    u8* oh8 = which == 0 ? oh80 : (which == 1 ? oh81 : nullptr);
    u8* ol8 = which == 0 ? ol80 : (which == 1 ? ol81 : nullptr);
    size_t i = ((size_t)blockIdx.x * blockDim.x + threadIdx.x) * 4;
    float4 v = *(const float4*)(in + i);
    uint2 h, l;
    split2h(v.x, v.y, h.x, l.x);
    split2h(v.z, v.w, h.y, l.y);
    *(uint2*)(oh + i) = h;
    *(uint2*)(ol + i) = l;
    if (oh8) {
        float hx = __half2float(__float2half_rn(v.x));
        float hy = __half2float(__float2half_rn(v.y));
        float hz = __half2float(__float2half_rn(v.z));
        float hw = __half2float(__float2half_rn(v.w));
        *(u32*)(oh8 + i) = (u32)to8(v.x * 0.0625f) | ((u32)to8(v.y * 0.0625f) << 8) |
                           ((u32)to8(v.z * 0.0625f) << 16) | ((u32)to8(v.w * 0.0625f) << 24);
        *(u32*)(ol8 + i) = (u32)to8((v.x - hx) * 128.f) | ((u32)to8((v.y - hy) * 128.f) << 8) |
                           ((u32)to8((v.z - hz) * 128.f) << 16) | ((u32)to8((v.w - hw) * 128.f) << 24);
    }
}

// sum KSPL_G partials over upper-tri tiles -> G f16+fp8 hi/lo, with mirror.
__global__ void gcombine_sym(const float* __restrict__ part, half* __restrict__ gh,
                             half* __restrict__ gl, u8* __restrict__ gh8,
                             u8* __restrict__ gl8)
{
    __shared__ float t[32][33];
    const int ti = c_ti[blockIdx.y], tj = c_tj[blockIdx.y];
    const int sxo = (blockIdx.x & 3) * 32, syo = (blockIdx.x >> 2) * 32;
    const int b = blockIdx.z;
    const int r0 = ti * 128 + syo, c0 = tj * 128 + sxo;
    const int tx = threadIdx.x, ty = threadIdx.y;
    const float* pz = part + (size_t)b * KSPL_G * CCSQ;
    half* ghb = gh + (size_t)b * CCSQ;
    half* glb = gl + (size_t)b * CCSQ;
    u8* gh8b = gh8 + (size_t)b * CCSQ;
    u8* gl8b = gl8 + (size_t)b * CCSQ;
#pragma unroll
    for (int p = 0; p < 4; p++) {
        const int r = r0 + ty + p * 8;
        const size_t w = (size_t)r * CC + c0 + tx;
        float s = pz[w] + pz[w + CCSQ] + pz[w + 2 * CCSQ] + pz[w + 3 * CCSQ];
        t[ty + p * 8][tx] = s;
        __half h = __float2half_rn(s);
        float lf = s - __half2float(h);
        ghb[w] = h;
        glb[w] = __float2half_rn(lf);
        gh8b[w] = to8(s * 0.0625f);
        gl8b[w] = to8(lf * 128.f);
    }
    if (ti != tj) {
        __syncthreads();
#pragma unroll
        for (int p = 0; p < 4; p++) {
            float s = t[tx][ty + p * 8];
            const size_t w = (size_t)(c0 + ty + p * 8) * CC + r0 + tx;
            __half h = __float2half_rn(s);
            float lf = s - __half2float(h);
            ghb[w] = h;
            glb[w] = __float2half_rn(lf);
            gh8b[w] = to8(s * 0.0625f);
            gl8b[w] = to8(lf * 128.f);
        }
    }
}

__global__ void matvec_w(const float* __restrict__ Wq, const float* __restrict__ Wk,
                         const float* __restrict__ sx, float* __restrict__ w1,
                         float* __restrict__ w2)
{
    const int w = threadIdx.x >> 5, lane = threadIdx.x & 31;
    const int c = blockIdx.x * 8 + w, b = blockIdx.z;
    const float* W = blockIdx.y ? Wk : Wq;
    float* outp = blockIdx.y ? w2 : w1;
    const float4* Wr = (const float4*)(W + (size_t)c * CC);
    const float4* sv = (const float4*)(sx + b * CC);
    float s = 0.f;
#pragma unroll
    for (int i = 0; i < 4; i++) {
        float4 a = Wr[lane + 32 * i], xv = sv[lane + 32 * i];
        s += a.x * xv.x + a.y * xv.y + a.z * xv.z + a.w * xv.w;
    }
#pragma unroll
    for (int o = 16; o > 0; o >>= 1) s += __shfl_xor_sync(~0u, s, o);
    if (lane == 0) outp[b * CC + c] = s;
}

// softmax + rank-1 corrections + pb = attn*bv; writes attn hi only
__global__ void softmax_corr(const float* __restrict__ d, const float* __restrict__ w1,
                             const float* __restrict__ w2, const float* __restrict__ bq,
                             const float* __restrict__ bk, const float* __restrict__ bv,
                             half* __restrict__ ah, float* __restrict__ pb)
{
    const int gw = (blockIdx.x * blockDim.x + threadIdx.x) >> 5;
    const int lane = threadIdx.x & 31;
    const int b = gw >> 9, c = gw & 511;
    const float bqc = bq[c], w1c = w1[b * CC + c];
    const float4* r = (const float4*)(d + (size_t)gw * CC);
    const float4* w2r = (const float4*)(w2 + b * CC);
    const float4* bkr = (const float4*)bk;
    const float4* bvr = (const float4*)bv;

    float4 v[4], bvv[4];
    float mx = -1e30f;
#pragma unroll
    for (int i = 0; i < 4; i++) {
        const int idx = lane + 32 * i;
        float4 dv = r[idx], w2v = w2r[idx], bkv = bkr[idx];
        bvv[i] = bvr[idx];
        v[i].x = dv.x + SCALE_F * (bqc * (w2v.x + (float)TT * bkv.x) + w1c * bkv.x);
        v[i].y = dv.y + SCALE_F * (bqc * (w2v.y + (float)TT * bkv.y) + w1c * bkv.y);
        v[i].z = dv.z + SCALE_F * (bqc * (w2v.z + (float)TT * bkv.z) + w1c * bkv.z);
        v[i].w = dv.w + SCALE_F * (bqc * (w2v.w + (float)TT * bkv.w) + w1c * bkv.w);
        mx = fmaxf(mx, fmaxf(fmaxf(v[i].x, v[i].y), fmaxf(v[i].z, v[i].w)));
    }
#pragma unroll
    for (int o = 16; o > 0; o >>= 1) mx = fmaxf(mx, __shfl_xor_sync(~0u, mx, o));
    float s = 0.f;
#pragma unroll
    for (int i = 0; i < 4; i++) {
        v[i].x = expf(v[i].x - mx); v[i].y = expf(v[i].y - mx);
        v[i].z = expf(v[i].z - mx); v[i].w = expf(v[i].w - mx);
        s += v[i].x + v[i].y + v[i].z + v[i].w;
    }
#pragma unroll
    for (int o = 16; o > 0; o >>= 1) s += __shfl_xor_sync(~0u, s, o);
    const float inv = 1.0f / s;
    float dotbv = 0.f;
#pragma unroll
    for (int i = 0; i < 4; i++) {
        v[i].x *= inv; v[i].y *= inv; v[i].z *= inv; v[i].w *= inv;
        dotbv += v[i].x * bvv[i].x + v[i].y * bvv[i].y + v[i].z * bvv[i].z + v[i].w * bvv[i].w;
        uint2 h;
        pack2h(v[i].x, v[i].y, h.x);
        pack2h(v[i].z, v[i].w, h.y);
        size_t o = (size_t)gw * CC + 4 * (lane + 32 * i);
        *(uint2*)(ah + o) = h;
    }
#pragma unroll
    for (int o = 16; o > 0; o >>= 1) dotbv += __shfl_xor_sync(~0u, dotbv, o);
    if (lane == 0) pb[gw] = dotbv;
}

// ---------------- launch ----------------
extern "C" void kernel_launch(void* const* d_in, const int* in_sizes, int n_in,
                              void* d_out, int out_size)
{
    (void)in_sizes; (void)n_in; (void)out_size;
    const float* x  = (const float*)d_in[0];
    const float* Wq = (const float*)d_in[1];
    const float* bq = (const float*)d_in[2];
    const float* Wk = (const float*)d_in[3];
    const float* bk = (const float*)d_in[4];
    const float* Wv = (const float*)d_in[5];
    const float* bv = (const float*)d_in[6];
    float* out = (float*)d_out;

    half *xh, *xl, *wqh, *wql, *wkh, *wkl, *wvh, *wvl;
    half *Gh, *Gl, *t2h, *t2l, *aH, *Ph, *Pl;
    u8 *xh8, *xl8, *wqh8, *wql8, *wkh8, *wkl8, *Gh8, *Gl8, *t2h8, *t2l8;
    float *part, *dots, *sx, *w1, *w2, *pb;
    cudaGetSymbolAddress((void**)&xh, g_x_h);
    cudaGetSymbolAddress((void**)&xl, g_x_l);
    cudaGetSymbolAddress((void**)&xh8, g_x_h8);
    cudaGetSymbolAddress((void**)&xl8, g_x_l8);
    cudaGetSymbolAddress((void**)&wqh, g_wq_h);
    cudaGetSymbolAddress((void**)&wql, g_wq_l);
    cudaGetSymbolAddress((void**)&wqh8, g_wq_h8);
    cudaGetSymbolAddress((void**)&wql8, g_wq_l8);
    cudaGetSymbolAddress((void**)&wkh, g_wk_h);
    cudaGetSymbolAddress((void**)&wkl, g_wk_l);
    cudaGetSymbolAddress((void**)&wkh8, g_wk_h8);
    cudaGetSymbolAddress((void**)&wkl8, g_wk_l8);
    cudaGetSymbolAddress((void**)&wvh, g_wv_h);
    cudaGetSymbolAddress((void**)&wvl, g_wv_l);
    cudaGetSymbolAddress((void**)&part, g_part);
    cudaGetSymbolAddress((void**)&Gh, g_G_h);
    cudaGetSymbolAddress((void**)&Gl, g_G_l);
    cudaGetSymbolAddress((void**)&Gh8, g_G_h8);
    cudaGetSymbolAddress((void**)&Gl8, g_G_l8);
    cudaGetSymbolAddress((void**)&t2h, g_t2_h);
    cudaGetSymbolAddress((void**)&t2l, g_t2_l);
    cudaGetSymbolAddress((void**)&t2h8, g_t2_h8);
    cudaGetSymbolAddress((void**)&t2l8, g_t2_l8);
    cudaGetSymbolAddress((void**)&dots, g_dots);
    cudaGetSymbolAddress((void**)&aH, g_a_h);
    cudaGetSymbolAddress((void**)&Ph, g_P_h);
    cudaGetSymbolAddress((void**)&Pl, g_P_l);
    cudaGetSymbolAddress((void**)&sx, g_sx);
    cudaGetSymbolAddress((void**)&w1, g_w1);
    cudaGetSymbolAddress((void**)&w2, g_w2);
    cudaGetSymbolAddress((void**)&pb, g_pb);

    const size_t CT = (size_t)CC * TT;
    const int SM_3 = 2 * 65536 + 1024;   // NPROD=3: f16 32K + fp8 32K per stage
    const int SM_1 = 2 * 32768 + 1024;   // NPROD=1

    cudaFuncSetAttribute(gemm_mma<false, false, KSPL_G, true, false, 3>, cudaFuncAttributeMaxDynamicSharedMemorySize, SM_3);
    cudaFuncSetAttribute(gemm_mma<false, true, 1, false, false, 3>, cudaFuncAttributeMaxDynamicSharedMemorySize, SM_3);
    cudaFuncSetAttribute(gemm_mma<false, false, 1, false, false, 3>, cudaFuncAttributeMaxDynamicSharedMemorySize, SM_3);
    cudaFuncSetAttribute(gemm_mma<false, true, 1, false, true, 1>, cudaFuncAttributeMaxDynamicSharedMemorySize, SM_1);
    cudaFuncSetAttribute(gemm_mma<true, false, 1, false, true, 1>, cudaFuncAttributeMaxDynamicSharedMemorySize, SM_1);

    // prep
    xsplit_sum<<<BB * CC, 256>>>(x, xh, xl, xh8, xl8, sx);
    esplit3<<<dim3(CCSQ / 1024, 3), 256>>>(Wq, Wk, Wv, wqh, wql, wkh, wkl, wvh, wvl,
                                           wqh8, wql8, wkh8, wkl8);
    matvec_w<<<dim3(CC / 8, 2, BB), 256>>>(Wq, Wk, sx, w1, w2);

    // G = x x^T : upper-triangle 128-tiles, split-K x4 partials
    gemm_mma<false, false, KSPL_G, true, false, 3><<<dim3(10, 1, BB * KSPL_G), 256, SM_3>>>(
        xh, xl, xh8, xl8, CT, TT, xh, xl, xh8, xl8, CT, TT,
        part, nullptr, nullptr, nullptr, nullptr,
        CCSQ, CC, nullptr, 0, 1.0f, TT / KSPL_G);
    gcombine_sym<<<dim3(16, 10, BB), dim3(32, 8)>>>(part, Gh, Gl, Gh8, Gl8);

    // t2 = Wq * G (split f16 + fp8 outputs)
    gemm_mma<false, true, 1, false, false, 3><<<dim3(4, 4, BB), 256, SM_3>>>(
        wqh, wql, wqh8, wql8, 0, CC, Gh, Gl, Gh8, Gl8, CCSQ, CC,
        nullptr, t2h, t2l, t2h8, t2l8,
        CCSQ, CC, nullptr, 0, 1.0f, CC);
    // dots = SCALE * t2 * Wk^T
    gemm_mma<false, false, 1, false, false, 3><<<dim3(4, 4, BB), 256, SM_3>>>(
        t2h, t2l, t2h8, t2l8, CCSQ, CC, wkh, wkl, wkh8, wkl8, 0, CC,
        dots, nullptr, nullptr, nullptr, nullptr,
        CCSQ, CC, nullptr, 0, SCALE_F, CC);
    // softmax + corrections + pb (attn hi only)
    softmax_corr<<<BB * CC / 4, 128>>>(dots, w1, w2, bq, bk, bv, aH, pb);
    // P = aH * Wv (1-product; split f16 output)
    gemm_mma<false, true, 1, false, true, 1><<<dim3(4, 4, BB), 256, SM_1>>>(
        aH, aH, nullptr, nullptr, CCSQ, CC, wvh, wvh, nullptr, nullptr, 0, CC,
        nullptr, Ph, Pl, nullptr, nullptr,
        CCSQ, CC, nullptr, 0, 1.0f, CC);
    // out = Ph * xh + pb (1-product)
    gemm_mma<true, false, 1, false, true, 1><<<dim3(TT / 128, CC / 128, BB), 256, SM_1>>>(
        Ph, Ph, nullptr, nullptr, CCSQ, CC, xh, xh, nullptr, nullptr, CT, TT,
        out, nullptr, nullptr, nullptr, nullptr,
        CT, TT, pb, CC, 1.0f, CC);
}